// round 6
// baseline (speedup 1.0000x reference)
#include <cuda_runtime.h>
#include <cuda_bf16.h>

#define MAXN 32768
#define MAXE 524288
#define MAXB 64

// ---------------- scratch (device globals; no allocation allowed) -------------
__device__ float g_qs[MAXN * 128];
__device__ float g_ks[MAXN * 128];
__device__ float g_curA[MAXN * 128];
__device__ float g_curB[MAXN * 128];
__device__ float g_acc[MAXN * 128];
__device__ float g_gcn[MAXN * 128];
__device__ float g_KV[MAXB * 128 * 128];
__device__ float g_vsum[MAXB * 128];
__device__ float g_ksum[MAXB * 128];
__device__ float g_denom[MAXN];
__device__ float g_dinv[MAXN];
__device__ float g_coef[MAXE];
__device__ int   g_ccol[MAXE];
__device__ int   g_cnt[MAXN];
__device__ int   g_rp[MAXN + 1];
__device__ int   g_curs[MAXN];
__device__ int   g_off[MAXB + 1];
__device__ int   g_batch[MAXN];
__device__ int   g_bsum[MAXB];

// ---------------- small utility kernels --------------------------------------
__global__ void k_zero_pre(int N) {
    int i = blockIdx.x * blockDim.x + threadIdx.x;
    if (i < N) { g_dinv[i] = 0.f; g_cnt[i] = 0; }
}

__global__ void k_zero_vsum(int n) {
    int i = blockIdx.x * blockDim.x + threadIdx.x;
    if (i < n) g_vsum[i] = 0.f;
}

__global__ void k_init(const float* __restrict__ x, int n) {
    int i = blockIdx.x * blockDim.x + threadIdx.x;
    if (i < n) { float v = x[i]; g_curA[i] = v; g_acc[i] = v; }
}

__global__ void k_offsets(const int* __restrict__ n_nodes, int B) {
    if (threadIdx.x == 0 && blockIdx.x == 0) {
        int s = 0;
        g_off[0] = 0;
        for (int b = 0; b < B; b++) { s += n_nodes[b]; g_off[b + 1] = s; }
    }
}

__global__ void k_batch(int N, int B) {
    int i = blockIdx.x * blockDim.x + threadIdx.x;
    if (i >= N) return;
    int lo = 0, hi = B;
    while (hi - lo > 1) {
        int mid = (lo + hi) >> 1;
        if (g_off[mid] <= i) lo = mid; else hi = mid;
    }
    g_batch[i] = lo;
}

// ---------------- GCN preprocessing -------------------------------------------
__global__ void k_deg(const int* __restrict__ row, const float* __restrict__ w, int E) {
    int e = blockIdx.x * blockDim.x + threadIdx.x;
    if (e < E) atomicAdd(&g_dinv[row[e]], w[e]);
}

__global__ void k_dinv(int N) {
    int i = blockIdx.x * blockDim.x + threadIdx.x;
    if (i < N) { float d = g_dinv[i]; g_dinv[i] = (d > 0.f) ? rsqrtf(d) : 0.f; }
}

__global__ void k_count(const int* __restrict__ row, int E) {
    int e = blockIdx.x * blockDim.x + threadIdx.x;
    if (e < E) atomicAdd(&g_cnt[row[e]], 1);
}

__global__ void k_scan1(int N) {
    __shared__ int s[512];
    int t = threadIdx.x;
    int gid = blockIdx.x * 512 + t;
    int v = (gid < N) ? g_cnt[gid] : 0;
    s[t] = v; __syncthreads();
    #pragma unroll
    for (int o = 1; o < 512; o <<= 1) {
        int add = (t >= o) ? s[t - o] : 0;
        __syncthreads();
        s[t] += add;
        __syncthreads();
    }
    if (gid < N) g_rp[gid + 1] = s[t];
    if (t == 511) g_bsum[blockIdx.x] = s[511];
}

__global__ void k_scan2(int nb) {
    __shared__ int s[64];
    int t = threadIdx.x;
    s[t] = (t < nb) ? g_bsum[t] : 0;
    __syncthreads();
    #pragma unroll
    for (int o = 1; o < 64; o <<= 1) {
        int add = (t >= o) ? s[t - o] : 0;
        __syncthreads();
        s[t] += add;
        __syncthreads();
    }
    if (t < nb) g_bsum[t] = s[t];
}

__global__ void k_scan3(int N) {
    int gid = blockIdx.x * blockDim.x + threadIdx.x;
    if (gid < N) {
        int blk = gid >> 9;
        int add = (blk > 0) ? g_bsum[blk - 1] : 0;
        g_rp[gid + 1] += add;
        if (gid == 0) g_rp[0] = 0;
    }
}

__global__ void k_cursor(int N) {
    int i = blockIdx.x * blockDim.x + threadIdx.x;
    if (i < N) g_curs[i] = g_rp[i];
}

__global__ void k_scatter(const int* __restrict__ row, const int* __restrict__ col,
                          const float* __restrict__ w, int E) {
    int e = blockIdx.x * blockDim.x + threadIdx.x;
    if (e >= E) return;
    int r = row[e], c = col[e];
    int p = atomicAdd(&g_curs[r], 1);
    g_ccol[p] = c;
    g_coef[p] = g_dinv[r] * g_dinv[c] * w[e];
}

// ---------------- dense GEMM: C[M,128] = A[M,128] @ W[128,128]^T (+bias) ------
// aSel: 0 -> Aext, 1 -> g_acc.   cSel: 0 -> g_qs, 1 -> g_ks, 2 -> Cext.
__global__ __launch_bounds__(256) void k_gemm(
    const float* __restrict__ Aext, int aSel,
    const float* __restrict__ W, const float* __restrict__ bias,
    float* __restrict__ Cext, int cSel, int M)
{
    const float* A = (aSel == 0) ? Aext : g_acc;
    float* Cout = (cSel == 0) ? g_qs : (cSel == 1) ? g_ks : Cext;

    __shared__ float As[16][64];    // [kk][row]
    __shared__ float Bs[16][132];   // [kk][j], padded

    int tid = threadIdx.x;
    int tx = tid & 15, ty = tid >> 4;
    int r0 = blockIdx.x * 64;

    float acc[4][8];
    #pragma unroll
    for (int r = 0; r < 4; r++)
        #pragma unroll
        for (int c = 0; c < 8; c++) acc[r][c] = 0.f;

    for (int k0 = 0; k0 < 128; k0 += 16) {
        {   // A tile (transposed into smem)
            int row = tid >> 2, kk4 = tid & 3;
            int gr = r0 + row;
            float4 v = make_float4(0.f, 0.f, 0.f, 0.f);
            if (gr < M) v = *(const float4*)(A + gr * 128 + k0 + kk4 * 4);
            As[kk4 * 4 + 0][row] = v.x;
            As[kk4 * 4 + 1][row] = v.y;
            As[kk4 * 4 + 2][row] = v.z;
            As[kk4 * 4 + 3][row] = v.w;
        }
        // W tile (transposed: Bs[kk][j] = W[j][k0+kk])
        #pragma unroll
        for (int it = 0; it < 8; it++) {
            int id = tid + it * 256;
            int kk = id & 15, j = id >> 4;
            Bs[kk][j] = W[j * 128 + k0 + kk];
        }
        __syncthreads();
        #pragma unroll
        for (int kk = 0; kk < 16; kk++) {
            float4 a  = *(const float4*)(&As[kk][ty * 4]);
            float4 b0 = *(const float4*)(&Bs[kk][tx * 8]);
            float4 b1 = *(const float4*)(&Bs[kk][tx * 8 + 4]);
            float av[4] = {a.x, a.y, a.z, a.w};
            float bv[8] = {b0.x, b0.y, b0.z, b0.w, b1.x, b1.y, b1.z, b1.w};
            #pragma unroll
            for (int r = 0; r < 4; r++)
                #pragma unroll
                for (int c = 0; c < 8; c++)
                    acc[r][c] += av[r] * bv[c];
        }
        __syncthreads();
    }
    #pragma unroll
    for (int r = 0; r < 4; r++) {
        int gr = r0 + ty * 4 + r;
        if (gr < M) {
            #pragma unroll
            for (int c = 0; c < 8; c++) {
                int j = tx * 8 + c;
                float b = bias ? bias[j] : 0.f;
                Cout[gr * 128 + j] = acc[r][c] + b;
            }
        }
    }
}

// ---------------- row L2-normalize (warp per node) ----------------------------
__global__ void k_norm(int sel, int N) {
    float* v = sel ? g_ks : g_qs;
    int warp = (blockIdx.x * blockDim.x + threadIdx.x) >> 5;
    int lane = threadIdx.x & 31;
    if (warp >= N) return;
    float4 q = *(const float4*)(v + warp * 128 + lane * 4);
    float s = q.x * q.x + q.y * q.y + q.z * q.z + q.w * q.w;
    #pragma unroll
    for (int o = 16; o > 0; o >>= 1) s += __shfl_xor_sync(0xFFFFFFFFu, s, o);
    float rn = rsqrtf(s);
    q.x *= rn; q.y *= rn; q.z *= rn; q.w *= rn;
    *(float4*)(v + warp * 128 + lane * 4) = q;
}

// ---------------- ksum per graph (block per graph, 128 threads) ---------------
__global__ void k_ksum() {
    int b = blockIdx.x;
    int d = threadIdx.x;
    int off = g_off[b], nb = g_off[b + 1] - off;
    float s = 0.f;
    for (int n = 0; n < nb; n++) s += g_ks[(off + n) * 128 + d];
    g_ksum[b * 128 + d] = s;
}

// ---------------- denom (warp per node; iteration-invariant) ------------------
__global__ void k_denom(int N) {
    int warp = (blockIdx.x * blockDim.x + threadIdx.x) >> 5;
    int lane = threadIdx.x & 31;
    if (warp >= N) return;
    int b = g_batch[warp];
    float4 q = *(const float4*)(g_qs + warp * 128 + lane * 4);
    float4 k = *(const float4*)(g_ksum + b * 128 + lane * 4);
    float s = q.x * k.x + q.y * k.y + q.z * k.z + q.w * k.w;
    #pragma unroll
    for (int o = 16; o > 0; o >>= 1) s += __shfl_xor_sync(0xFFFFFFFFu, s, o);
    if (lane == 0) g_denom[warp] = s + (float)(g_off[b + 1] - g_off[b]);
}

// ---------------- GCN gather (warp per node, lane = float4 channel chunk) -----
__global__ __launch_bounds__(256) void k_gcn(int curSel, int N) {
    const float* cur = curSel ? g_curB : g_curA;
    int warp = (blockIdx.x * blockDim.x + threadIdx.x) >> 5;
    int lane = threadIdx.x & 31;
    if (warp >= N) return;
    int s = g_rp[warp], e = g_rp[warp + 1];
    float4 a = make_float4(0.f, 0.f, 0.f, 0.f);
    for (int p = s; p < e; p++) {
        float cf = g_coef[p];
        int cl = g_ccol[p];
        float4 v = *(const float4*)(cur + cl * 128 + lane * 4);
        a.x += cf * v.x; a.y += cf * v.y; a.z += cf * v.z; a.w += cf * v.w;
    }
    *(float4*)(g_gcn + warp * 128 + lane * 4) = a;
}

// ---------------- KV = K^T V per graph + column sums of V ---------------------
__global__ __launch_bounds__(256) void k_kv(int curSel) {
    const float* cur = curSel ? g_curB : g_curA;
    __shared__ float Ks[16][128];
    __shared__ float Vs[16][128];
    int b = blockIdx.x;
    int off = g_off[b], nb = g_off[b + 1] - off;
    int tid = threadIdx.x, tx = tid & 15, ty = tid >> 4;
    int d4 = tid & 31;

    float acc[8][8];
    #pragma unroll
    for (int r = 0; r < 8; r++)
        #pragma unroll
        for (int c = 0; c < 8; c++) acc[r][c] = 0.f;
    float4 vpart = make_float4(0.f, 0.f, 0.f, 0.f);

    for (int k0 = 0; k0 < nb; k0 += 16) {
        #pragma unroll
        for (int it = 0; it < 2; it++) {
            int id = tid + it * 256;
            int kk = id >> 5, dd = id & 31;
            int r = off + k0 + kk;
            float4 kv = make_float4(0.f, 0.f, 0.f, 0.f);
            float4 vv = make_float4(0.f, 0.f, 0.f, 0.f);
            if (k0 + kk < nb) {
                kv = *(const float4*)(g_ks + r * 128 + dd * 4);
                vv = *(const float4*)(cur + r * 128 + dd * 4);
            }
            *(float4*)(&Ks[kk][dd * 4]) = kv;
            *(float4*)(&Vs[kk][dd * 4]) = vv;
            vpart.x += vv.x; vpart.y += vv.y; vpart.z += vv.z; vpart.w += vv.w;
        }
        __syncthreads();
        #pragma unroll
        for (int kk = 0; kk < 16; kk++) {
            float4 a0 = *(const float4*)(&Ks[kk][ty * 8]);
            float4 a1 = *(const float4*)(&Ks[kk][ty * 8 + 4]);
            float4 b0 = *(const float4*)(&Vs[kk][tx * 8]);
            float4 b1 = *(const float4*)(&Vs[kk][tx * 8 + 4]);
            float av[8] = {a0.x, a0.y, a0.z, a0.w, a1.x, a1.y, a1.z, a1.w};
            float bv[8] = {b0.x, b0.y, b0.z, b0.w, b1.x, b1.y, b1.z, b1.w};
            #pragma unroll
            for (int r = 0; r < 8; r++)
                #pragma unroll
                for (int c = 0; c < 8; c++)
                    acc[r][c] += av[r] * bv[c];
        }
        __syncthreads();
    }

    float* out = g_KV + b * 16384;
    #pragma unroll
    for (int r = 0; r < 8; r++) {
        int cr = ty * 8 + r;
        float4 o0 = make_float4(acc[r][0], acc[r][1], acc[r][2], acc[r][3]);
        float4 o1 = make_float4(acc[r][4], acc[r][5], acc[r][6], acc[r][7]);
        *(float4*)(out + cr * 128 + tx * 8)     = o0;
        *(float4*)(out + cr * 128 + tx * 8 + 4) = o1;
    }
    atomicAdd(&g_vsum[b * 128 + d4 * 4 + 0], vpart.x);
    atomicAdd(&g_vsum[b * 128 + d4 * 4 + 1], vpart.y);
    atomicAdd(&g_vsum[b * 128 + d4 * 4 + 2], vpart.z);
    atomicAdd(&g_vsum[b * 128 + d4 * 4 + 3], vpart.w);
}

// ---------------- numer = Q @ KV, fused combine + accumulate ------------------
// grid: (ceil(N/64), B). curSel: 0 -> cur=g_curA next=g_curB; 1 -> swapped.
__global__ __launch_bounds__(256) void k_numer(int curSel) {
    float* nxt = curSel ? g_curA : g_curB;
    __shared__ float As[16][64];
    __shared__ float Bs[16][132];

    int b = blockIdx.y;
    int off = g_off[b], nb = g_off[b + 1] - off;
    int r0 = blockIdx.x * 64;
    if (r0 >= nb) return;
    int base = off + r0;
    int m = nb - r0; if (m > 64) m = 64;

    const float* KVb = g_KV + b * 16384;
    int tid = threadIdx.x, tx = tid & 15, ty = tid >> 4;

    float acc[4][8];
    #pragma unroll
    for (int r = 0; r < 4; r++)
        #pragma unroll
        for (int c = 0; c < 8; c++) acc[r][c] = 0.f;

    for (int k0 = 0; k0 < 128; k0 += 16) {
        {   // A tile from qs
            int row = tid >> 2, kk4 = tid & 3;
            float4 v = make_float4(0.f, 0.f, 0.f, 0.f);
            if (row < m) v = *(const float4*)(g_qs + (base + row) * 128 + k0 + kk4 * 4);
            As[kk4 * 4 + 0][row] = v.x;
            As[kk4 * 4 + 1][row] = v.y;
            As[kk4 * 4 + 2][row] = v.z;
            As[kk4 * 4 + 3][row] = v.w;
        }
        // B tile from KV (no transpose)
        #pragma unroll
        for (int it = 0; it < 2; it++) {
            int id = tid + it * 256;
            int kk = id >> 5, j4 = id & 31;
            float4 v = *(const float4*)(KVb + (k0 + kk) * 128 + j4 * 4);
            *(float4*)(&Bs[kk][j4 * 4]) = v;
        }
        __syncthreads();
        #pragma unroll
        for (int kk = 0; kk < 16; kk++) {
            float4 a  = *(const float4*)(&As[kk][ty * 4]);
            float4 b0 = *(const float4*)(&Bs[kk][tx * 8]);
            float4 b1 = *(const float4*)(&Bs[kk][tx * 8 + 4]);
            float av[4] = {a.x, a.y, a.z, a.w};
            float bv[8] = {b0.x, b0.y, b0.z, b0.w, b1.x, b1.y, b1.z, b1.w};
            #pragma unroll
            for (int r = 0; r < 4; r++)
                #pragma unroll
                for (int c = 0; c < 8; c++)
                    acc[r][c] += av[r] * bv[c];
        }
        __syncthreads();
    }

    #pragma unroll
    for (int r = 0; r < 4; r++) {
        int row = ty * 4 + r;
        if (row < m) {
            int gi = base + row;
            float inv = 1.f / g_denom[gi];
            #pragma unroll
            for (int c = 0; c < 8; c++) {
                int j = tx * 8 + c;
                float attn = (acc[r][c] + g_vsum[b * 128 + j]) * inv;
                float v = 0.5f * g_gcn[gi * 128 + j] + 0.5f * attn;
                nxt[gi * 128 + j] = v;
                g_acc[gi * 128 + j] += v;
            }
        }
    }
}

// ---------------- launch -------------------------------------------------------
extern "C" void kernel_launch(void* const* d_in, const int* in_sizes, int n_in,
                              void* d_out, int out_size) {
    const float* x    = (const float*)d_in[0];
    const int*   ei   = (const int*)d_in[1];
    const float* ew   = (const float*)d_in[2];
    const int*   nn   = (const int*)d_in[3];
    const float* Wq_w = (const float*)d_in[4];
    const float* Wq_b = (const float*)d_in[5];
    const float* Wk_w = (const float*)d_in[6];
    const float* Wk_b = (const float*)d_in[7];
    const float* Wo_w = (const float*)d_in[8];
    const float* Wo_b = (const float*)d_in[9];

    int N = in_sizes[0] / 128;
    int E = in_sizes[1] / 2;
    int B = in_sizes[3];
    const int* row = ei;
    const int* col = ei + E;

    int gN = (N + 255) / 256;
    int gE = (E + 255) / 256;

    // preprocessing
    k_zero_pre<<<gN, 256>>>(N);
    k_offsets<<<1, 32>>>(nn, B);
    k_batch<<<gN, 256>>>(N, B);
    k_deg<<<gE, 256>>>(row, ew, E);
    k_dinv<<<gN, 256>>>(N);
    k_count<<<gE, 256>>>(row, E);
    k_scan1<<<(N + 511) / 512, 512>>>(N);
    k_scan2<<<1, 64>>>((N + 511) / 512);
    k_scan3<<<gN, 256>>>(N);
    k_cursor<<<gN, 256>>>(N);
    k_scatter<<<gE, 256>>>(row, col, ew, E);

    // q, k projections + normalize; iteration-invariant denom
    int gG = (N + 63) / 64;
    k_gemm<<<gG, 256>>>(x, 0, Wq_w, Wq_b, nullptr, 0, N);
    k_norm<<<(N + 7) / 8, 256>>>(0, N);
    k_gemm<<<gG, 256>>>(x, 0, Wk_w, Wk_b, nullptr, 1, N);
    k_norm<<<(N + 7) / 8, 256>>>(1, N);
    k_ksum<<<B, 128>>>();
    k_denom<<<(N + 7) / 8, 256>>>(N);

    // cur = acc = x
    k_init<<<(N * 128 + 255) / 256, 256>>>(x, N * 128);

    // 4 propagation iterations
    for (int it = 0; it < 4; it++) {
        int cs = it & 1;
        k_gcn<<<(N + 7) / 8, 256>>>(cs, N);
        k_zero_vsum<<<(B * 128 + 255) / 256, 256>>>(B * 128);
        k_kv<<<B, 256>>>(cs);
        dim3 g(gG, B);
        k_numer<<<g, 256>>>(cs);
    }

    // out = acc @ Wo^T + bias  (H=1 so /H is a no-op)
    k_gemm<<<gG, 256>>>(nullptr, 1, Wo_w, Wo_b, (float*)d_out, 2, N);
}

// round 7
// speedup vs baseline: 1.5492x; 1.5492x over previous
#include <cuda_runtime.h>
#include <cuda_bf16.h>

#define MAXN 32768
#define MAXE 524288
#define MAXB 64
#define KVS 8   // split-K factor for k_kv

// ---------------- scratch (device globals; no allocation allowed) -------------
__device__ float g_qs[MAXN * 128];
__device__ float g_ks[MAXN * 128];
__device__ float g_curA[MAXN * 128];
__device__ float g_curB[MAXN * 128];
__device__ float g_acc[MAXN * 128];
__device__ float g_gcn[MAXN * 128];
__device__ float g_KV[MAXB * 128 * 128];
__device__ float g_KVp[KVS * MAXB * 128 * 128];
__device__ float g_vsum[MAXB * 128];
__device__ float g_vsump[KVS * MAXB * 128];
__device__ float g_ksum[MAXB * 128];
__device__ float g_denom[MAXN];
__device__ float g_dinv[MAXN];
__device__ float g_coef[MAXE];
__device__ int   g_ccol[MAXE];
__device__ int   g_cnt[MAXN];
__device__ int   g_rp[MAXN + 1];
__device__ int   g_curs[MAXN];
__device__ int   g_off[MAXB + 1];
__device__ int   g_batch[MAXN];
__device__ int   g_bsum[MAXB];

// ---------------- f32x2 helpers ------------------------------------------------
#define FMA2(acc, a, b) \
    asm("fma.rn.f32x2 %0, %1, %2, %0;" : "+l"(acc) : "l"(a), "l"(b))

__device__ __forceinline__ unsigned long long pk2(float v) {
    unsigned long long d;
    unsigned int u = __float_as_uint(v);
    asm("mov.b64 %0, {%1, %1};" : "=l"(d) : "r"(u));
    return d;
}
__device__ __forceinline__ void upk2(unsigned long long v, float& lo, float& hi) {
    unsigned int a, b;
    asm("mov.b64 {%0, %1}, %2;" : "=r"(a), "=r"(b) : "l"(v));
    lo = __uint_as_float(a); hi = __uint_as_float(b);
}

// ---------------- small utility kernels --------------------------------------
__global__ void k_init(const float* __restrict__ x, int n) {
    int i = blockIdx.x * blockDim.x + threadIdx.x;
    if (i < n) { float v = x[i]; g_curA[i] = v; g_acc[i] = v; }
}

__global__ void k_offsets(const int* __restrict__ n_nodes, int B) {
    if (threadIdx.x == 0 && blockIdx.x == 0) {
        int s = 0;
        g_off[0] = 0;
        for (int b = 0; b < B; b++) { s += n_nodes[b]; g_off[b + 1] = s; }
    }
}

// batch id per node + zero init for degree/count
__global__ void k_batch(int N, int B) {
    int i = blockIdx.x * blockDim.x + threadIdx.x;
    if (i >= N) return;
    int lo = 0, hi = B;
    while (hi - lo > 1) {
        int mid = (lo + hi) >> 1;
        if (g_off[mid] <= i) lo = mid; else hi = mid;
    }
    g_batch[i] = lo;
    g_dinv[i] = 0.f;
    g_cnt[i] = 0;
}

// ---------------- GCN preprocessing -------------------------------------------
__global__ void k_degcnt(const int* __restrict__ row, const float* __restrict__ w, int E) {
    int e = blockIdx.x * blockDim.x + threadIdx.x;
    if (e < E) {
        int r = row[e];
        atomicAdd(&g_dinv[r], w[e]);
        atomicAdd(&g_cnt[r], 1);
    }
}

__global__ void k_dinv(int N) {
    int i = blockIdx.x * blockDim.x + threadIdx.x;
    if (i < N) { float d = g_dinv[i]; g_dinv[i] = (d > 0.f) ? rsqrtf(d) : 0.f; }
}

__global__ void k_scan1(int N) {
    __shared__ int s[512];
    int t = threadIdx.x;
    int gid = blockIdx.x * 512 + t;
    int v = (gid < N) ? g_cnt[gid] : 0;
    s[t] = v; __syncthreads();
    #pragma unroll
    for (int o = 1; o < 512; o <<= 1) {
        int add = (t >= o) ? s[t - o] : 0;
        __syncthreads();
        s[t] += add;
        __syncthreads();
    }
    if (gid < N) g_rp[gid + 1] = s[t];
    if (t == 511) g_bsum[blockIdx.x] = s[511];
}

__global__ void k_scan2(int nb) {
    __shared__ int s[64];
    int t = threadIdx.x;
    s[t] = (t < nb) ? g_bsum[t] : 0;
    __syncthreads();
    #pragma unroll
    for (int o = 1; o < 64; o <<= 1) {
        int add = (t >= o) ? s[t - o] : 0;
        __syncthreads();
        s[t] += add;
        __syncthreads();
    }
    if (t < nb) g_bsum[t] = s[t];
}

__global__ void k_scan3(int N) {
    int gid = blockIdx.x * blockDim.x + threadIdx.x;
    if (gid < N) {
        int blk = gid >> 9;
        int add = (blk > 0) ? g_bsum[blk - 1] : 0;
        g_rp[gid + 1] += add;
        if (gid == 0) g_rp[0] = 0;
    }
}

__global__ void k_cursor(int N) {
    int i = blockIdx.x * blockDim.x + threadIdx.x;
    if (i < N) g_curs[i] = g_rp[i];
}

__global__ void k_scatter(const int* __restrict__ row, const int* __restrict__ col,
                          const float* __restrict__ w, int E) {
    int e = blockIdx.x * blockDim.x + threadIdx.x;
    if (e >= E) return;
    int r = row[e], c = col[e];
    int p = atomicAdd(&g_curs[r], 1);
    g_ccol[p] = c;
    g_coef[p] = g_dinv[r] * g_dinv[c] * w[e];
}

// ---------------- dense GEMM: C[M,128] = A[M,128] @ W[128,128]^T (+bias) ------
// 128x128 tile per 256-thread block, f32x2 packed FMA.
// aSel: 0 -> Aext, 1 -> g_acc.   cSel: 0 -> g_qs, 1 -> g_ks, 2 -> Cext.
__global__ __launch_bounds__(256) void k_gemm(
    const float* __restrict__ Aext, int aSel,
    const float* __restrict__ W, const float* __restrict__ bias,
    float* __restrict__ Cext, int cSel, int M)
{
    const float* A = (aSel == 0) ? Aext : g_acc;
    float* Cout = (cSel == 0) ? g_qs : (cSel == 1) ? g_ks : Cext;

    __shared__ __align__(16) float As[16][128];   // [kk][row]
    __shared__ __align__(16) float Bs[16][132];   // [kk][j]

    int tid = threadIdx.x;
    int tx = tid & 15, ty = tid >> 4;
    int r0 = blockIdx.x * 128;

    unsigned long long acc2[8][4];
    #pragma unroll
    for (int r = 0; r < 8; r++)
        #pragma unroll
        for (int c = 0; c < 4; c++) acc2[r][c] = 0ULL;

    for (int k0 = 0; k0 < 128; k0 += 16) {
        // A tile (transpose into smem): 128 rows x 16 k
        #pragma unroll
        for (int it = 0; it < 2; it++) {
            int id = tid + it * 256;
            int rowi = id >> 2, k4 = id & 3;
            int gr = r0 + rowi;
            float4 v = make_float4(0.f, 0.f, 0.f, 0.f);
            if (gr < M) v = *(const float4*)(A + gr * 128 + k0 + k4 * 4);
            As[k4 * 4 + 0][rowi] = v.x;
            As[k4 * 4 + 1][rowi] = v.y;
            As[k4 * 4 + 2][rowi] = v.z;
            As[k4 * 4 + 3][rowi] = v.w;
        }
        // W tile (transposed: Bs[kk][j] = W[j][k0+kk])
        #pragma unroll
        for (int it = 0; it < 8; it++) {
            int id = tid + it * 256;
            int kk = id & 15, j = id >> 4;
            Bs[kk][j] = W[j * 128 + k0 + kk];
        }
        __syncthreads();
        #pragma unroll
        for (int kk = 0; kk < 16; kk++) {
            float4 a0 = *(const float4*)(&As[kk][ty * 8]);
            float4 a1 = *(const float4*)(&As[kk][ty * 8 + 4]);
            ulonglong2 bA = *(const ulonglong2*)(&Bs[kk][tx * 8]);
            ulonglong2 bB = *(const ulonglong2*)(&Bs[kk][tx * 8 + 4]);
            float av[8] = {a0.x, a0.y, a0.z, a0.w, a1.x, a1.y, a1.z, a1.w};
            #pragma unroll
            for (int r = 0; r < 8; r++) {
                unsigned long long ap = pk2(av[r]);
                FMA2(acc2[r][0], ap, bA.x);
                FMA2(acc2[r][1], ap, bA.y);
                FMA2(acc2[r][2], ap, bB.x);
                FMA2(acc2[r][3], ap, bB.y);
            }
        }
        __syncthreads();
    }

    float4 bs0 = make_float4(0.f, 0.f, 0.f, 0.f), bs1 = bs0;
    if (bias) {
        bs0 = *(const float4*)(bias + tx * 8);
        bs1 = *(const float4*)(bias + tx * 8 + 4);
    }
    #pragma unroll
    for (int r = 0; r < 8; r++) {
        int gr = r0 + ty * 8 + r;
        if (gr < M) {
            float o[8];
            upk2(acc2[r][0], o[0], o[1]);
            upk2(acc2[r][1], o[2], o[3]);
            upk2(acc2[r][2], o[4], o[5]);
            upk2(acc2[r][3], o[6], o[7]);
            float4 w0 = make_float4(o[0] + bs0.x, o[1] + bs0.y, o[2] + bs0.z, o[3] + bs0.w);
            float4 w1 = make_float4(o[4] + bs1.x, o[5] + bs1.y, o[6] + bs1.z, o[7] + bs1.w);
            *(float4*)(Cout + gr * 128 + tx * 8)     = w0;
            *(float4*)(Cout + gr * 128 + tx * 8 + 4) = w1;
        }
    }
}

// ---------------- row L2-normalize (warp per node) ----------------------------
__global__ void k_norm(int sel, int N) {
    float* v = sel ? g_ks : g_qs;
    int warp = (blockIdx.x * blockDim.x + threadIdx.x) >> 5;
    int lane = threadIdx.x & 31;
    if (warp >= N) return;
    float4 q = *(const float4*)(v + warp * 128 + lane * 4);
    float s = q.x * q.x + q.y * q.y + q.z * q.z + q.w * q.w;
    #pragma unroll
    for (int o = 16; o > 0; o >>= 1) s += __shfl_xor_sync(0xFFFFFFFFu, s, o);
    float rn = rsqrtf(s);
    q.x *= rn; q.y *= rn; q.z *= rn; q.w *= rn;
    *(float4*)(v + warp * 128 + lane * 4) = q;
}

// ---------------- ksum per graph (block per graph, 512 threads) ---------------
__global__ __launch_bounds__(512) void k_ksum() {
    __shared__ float red[512];
    int b = blockIdx.x;
    int tid = threadIdx.x;
    int d = tid & 127, c = tid >> 7;
    int off = g_off[b], nb = g_off[b + 1] - off;
    float s = 0.f;
    for (int n = c; n < nb; n += 4) s += g_ks[(off + n) * 128 + d];
    red[c * 128 + d] = s;
    __syncthreads();
    if (tid < 128)
        g_ksum[b * 128 + tid] = red[tid] + red[tid + 128] + red[tid + 256] + red[tid + 384];
}

// ---------------- denom (warp per node; iteration-invariant) ------------------
__global__ void k_denom(int N) {
    int warp = (blockIdx.x * blockDim.x + threadIdx.x) >> 5;
    int lane = threadIdx.x & 31;
    if (warp >= N) return;
    int b = g_batch[warp];
    float4 q = *(const float4*)(g_qs + warp * 128 + lane * 4);
    float4 k = *(const float4*)(g_ksum + b * 128 + lane * 4);
    float s = q.x * k.x + q.y * k.y + q.z * k.z + q.w * k.w;
    #pragma unroll
    for (int o = 16; o > 0; o >>= 1) s += __shfl_xor_sync(0xFFFFFFFFu, s, o);
    if (lane == 0) g_denom[warp] = s + (float)(g_off[b + 1] - g_off[b]);
}

// ---------------- GCN gather (warp per node, lane = float4 channel chunk) -----
__global__ __launch_bounds__(256) void k_gcn(int curSel, int N) {
    const float* cur = curSel ? g_curB : g_curA;
    int warp = (blockIdx.x * blockDim.x + threadIdx.x) >> 5;
    int lane = threadIdx.x & 31;
    if (warp >= N) return;
    int s = g_rp[warp], e = g_rp[warp + 1];
    float4 a = make_float4(0.f, 0.f, 0.f, 0.f);
    for (int p = s; p < e; p++) {
        float cf = g_coef[p];
        int cl = g_ccol[p];
        float4 v = *(const float4*)(cur + cl * 128 + lane * 4);
        a.x += cf * v.x; a.y += cf * v.y; a.z += cf * v.z; a.w += cf * v.w;
    }
    *(float4*)(g_gcn + warp * 128 + lane * 4) = a;
}

// ---------------- split-K partial KV = K^T V per graph + V column sums --------
// grid (B, KVS). Each CTA handles a chunk of the graph's nodes.
__global__ __launch_bounds__(256) void k_kv(int curSel) {
    const float* cur = curSel ? g_curB : g_curA;
    __shared__ __align__(16) float Ks[16][132];
    __shared__ __align__(16) float Vs[16][132];
    __shared__ float vs[128];
    int b = blockIdx.x, sp = blockIdx.y;
    int off = g_off[b], nb = g_off[b + 1] - off;
    int chunk = (nb + KVS - 1) / KVS;
    int s0 = sp * chunk;
    int lim = s0 + chunk; if (lim > nb) lim = nb;

    int tid = threadIdx.x, tx = tid & 15, ty = tid >> 4;

    if (tid < 128) vs[tid] = 0.f;
    __syncthreads();

    unsigned long long acc2[8][4];
    #pragma unroll
    for (int r = 0; r < 8; r++)
        #pragma unroll
        for (int c = 0; c < 4; c++) acc2[r][c] = 0ULL;
    float4 vpart = make_float4(0.f, 0.f, 0.f, 0.f);

    for (int k0 = s0; k0 < lim; k0 += 16) {
        #pragma unroll
        for (int it = 0; it < 2; it++) {
            int id = tid + it * 256;
            int kk = id >> 5, dd = id & 31;
            int rl = k0 + kk;
            float4 kv = make_float4(0.f, 0.f, 0.f, 0.f);
            float4 vv = make_float4(0.f, 0.f, 0.f, 0.f);
            if (rl < lim) {
                kv = *(const float4*)(g_ks + (off + rl) * 128 + dd * 4);
                vv = *(const float4*)(cur + (off + rl) * 128 + dd * 4);
            }
            *(float4*)(&Ks[kk][dd * 4]) = kv;
            *(float4*)(&Vs[kk][dd * 4]) = vv;
            vpart.x += vv.x; vpart.y += vv.y; vpart.z += vv.z; vpart.w += vv.w;
        }
        __syncthreads();
        #pragma unroll
        for (int kk = 0; kk < 16; kk++) {
            float4 a0 = *(const float4*)(&Ks[kk][ty * 8]);
            float4 a1 = *(const float4*)(&Ks[kk][ty * 8 + 4]);
            ulonglong2 bA = *(const ulonglong2*)(&Vs[kk][tx * 8]);
            ulonglong2 bB = *(const ulonglong2*)(&Vs[kk][tx * 8 + 4]);
            float av[8] = {a0.x, a0.y, a0.z, a0.w, a1.x, a1.y, a1.z, a1.w};
            #pragma unroll
            for (int r = 0; r < 8; r++) {
                unsigned long long ap = pk2(av[r]);
                FMA2(acc2[r][0], ap, bA.x);
                FMA2(acc2[r][1], ap, bA.y);
                FMA2(acc2[r][2], ap, bB.x);
                FMA2(acc2[r][3], ap, bB.y);
            }
        }
        __syncthreads();
    }

    float* out = g_KVp + (sp * MAXB + b) * 16384;
    #pragma unroll
    for (int r = 0; r < 8; r++) {
        int cr = ty * 8 + r;
        float o[8];
        upk2(acc2[r][0], o[0], o[1]);
        upk2(acc2[r][1], o[2], o[3]);
        upk2(acc2[r][2], o[4], o[5]);
        upk2(acc2[r][3], o[6], o[7]);
        *(float4*)(out + cr * 128 + tx * 8)     = make_float4(o[0], o[1], o[2], o[3]);
        *(float4*)(out + cr * 128 + tx * 8 + 4) = make_float4(o[4], o[5], o[6], o[7]);
    }

    // V column-sum partial for this chunk (smem reduce, no global atomics)
    int d4 = tid & 31;
    atomicAdd(&vs[d4 * 4 + 0], vpart.x);
    atomicAdd(&vs[d4 * 4 + 1], vpart.y);
    atomicAdd(&vs[d4 * 4 + 2], vpart.z);
    atomicAdd(&vs[d4 * 4 + 3], vpart.w);
    __syncthreads();
    if (tid < 128) g_vsump[(sp * MAXB + b) * 128 + tid] = vs[tid];
}

// ---------------- reduce split-K partials -------------------------------------
// grid (B, 129): y<128 -> KV row y; y==128 -> vsum row.
__global__ void k_kvred() {
    int b = blockIdx.x, r = blockIdx.y, t = threadIdx.x;
    if (r < 128) {
        float s = 0.f;
        #pragma unroll
        for (int sp = 0; sp < KVS; sp++)
            s += g_KVp[(sp * MAXB + b) * 16384 + r * 128 + t];
        g_KV[b * 16384 + r * 128 + t] = s;
    } else {
        float s = 0.f;
        #pragma unroll
        for (int sp = 0; sp < KVS; sp++)
            s += g_vsump[(sp * MAXB + b) * 128 + t];
        g_vsum[b * 128 + t] = s;
    }
}

// ---------------- numer = Q @ KV, fused combine + accumulate ------------------
// grid: (ceil(N/128), B). 128x128 tile, f32x2.
__global__ __launch_bounds__(256) void k_numer(int curSel) {
    float* nxt = curSel ? g_curA : g_curB;
    __shared__ __align__(16) float As[16][128];
    __shared__ __align__(16) float Bs[16][132];

    int b = blockIdx.y;
    int off = g_off[b], nb = g_off[b + 1] - off;
    int r0 = blockIdx.x * 128;
    if (r0 >= nb) return;
    int base = off + r0;
    int m = nb - r0; if (m > 128) m = 128;

    const float* KVb = g_KV + b * 16384;
    int tid = threadIdx.x, tx = tid & 15, ty = tid >> 4;

    unsigned long long acc2[8][4];
    #pragma unroll
    for (int r = 0; r < 8; r++)
        #pragma unroll
        for (int c = 0; c < 4; c++) acc2[r][c] = 0ULL;

    for (int k0 = 0; k0 < 128; k0 += 16) {
        // A tile from qs (transpose)
        #pragma unroll
        for (int it = 0; it < 2; it++) {
            int id = tid + it * 256;
            int rowi = id >> 2, k4 = id & 3;
            float4 v = make_float4(0.f, 0.f, 0.f, 0.f);
            if (rowi < m) v = *(const float4*)(g_qs + (base + rowi) * 128 + k0 + k4 * 4);
            As[k4 * 4 + 0][rowi] = v.x;
            As[k4 * 4 + 1][rowi] = v.y;
            As[k4 * 4 + 2][rowi] = v.z;
            As[k4 * 4 + 3][rowi] = v.w;
        }
        // B tile from KV (no transpose)
        #pragma unroll
        for (int it = 0; it < 2; it++) {
            int id = tid + it * 256;
            int kk = id >> 5, j4 = id & 31;
            float4 v = *(const float4*)(KVb + (k0 + kk) * 128 + j4 * 4);
            *(float4*)(&Bs[kk][j4 * 4]) = v;
        }
        __syncthreads();
        #pragma unroll
        for (int kk = 0; kk < 16; kk++) {
            float4 a0 = *(const float4*)(&As[kk][ty * 8]);
            float4 a1 = *(const float4*)(&As[kk][ty * 8 + 4]);
            ulonglong2 bA = *(const ulonglong2*)(&Bs[kk][tx * 8]);
            ulonglong2 bB = *(const ulonglong2*)(&Bs[kk][tx * 8 + 4]);
            float av[8] = {a0.x, a0.y, a0.z, a0.w, a1.x, a1.y, a1.z, a1.w};
            #pragma unroll
            for (int r = 0; r < 8; r++) {
                unsigned long long ap = pk2(av[r]);
                FMA2(acc2[r][0], ap, bA.x);
                FMA2(acc2[r][1], ap, bA.y);
                FMA2(acc2[r][2], ap, bB.x);
                FMA2(acc2[r][3], ap, bB.y);
            }
        }
        __syncthreads();
    }

    float4 vs0 = *(const float4*)(g_vsum + b * 128 + tx * 8);
    float4 vs1 = *(const float4*)(g_vsum + b * 128 + tx * 8 + 4);
    float vsv[8] = {vs0.x, vs0.y, vs0.z, vs0.w, vs1.x, vs1.y, vs1.z, vs1.w};

    #pragma unroll
    for (int r = 0; r < 8; r++) {
        int rowi = ty * 8 + r;
        if (rowi < m) {
            int gi = base + rowi;
            float inv = 1.f / g_denom[gi];
            float o[8];
            upk2(acc2[r][0], o[0], o[1]);
            upk2(acc2[r][1], o[2], o[3]);
            upk2(acc2[r][2], o[4], o[5]);
            upk2(acc2[r][3], o[6], o[7]);
            float4 gc0 = *(const float4*)(g_gcn + gi * 128 + tx * 8);
            float4 gc1 = *(const float4*)(g_gcn + gi * 128 + tx * 8 + 4);
            float gcv[8] = {gc0.x, gc0.y, gc0.z, gc0.w, gc1.x, gc1.y, gc1.z, gc1.w};
            float4 ac0 = *(const float4*)(g_acc + gi * 128 + tx * 8);
            float4 ac1 = *(const float4*)(g_acc + gi * 128 + tx * 8 + 4);
            float acv[8] = {ac0.x, ac0.y, ac0.z, ac0.w, ac1.x, ac1.y, ac1.z, ac1.w};
            float nv[8];
            #pragma unroll
            for (int c = 0; c < 8; c++) {
                float attn = (o[c] + vsv[c]) * inv;
                nv[c] = 0.5f * gcv[c] + 0.5f * attn;
                acv[c] += nv[c];
            }
            *(float4*)(nxt + gi * 128 + tx * 8)     = make_float4(nv[0], nv[1], nv[2], nv[3]);
            *(float4*)(nxt + gi * 128 + tx * 8 + 4) = make_float4(nv[4], nv[5], nv[6], nv[7]);
            *(float4*)(g_acc + gi * 128 + tx * 8)     = make_float4(acv[0], acv[1], acv[2], acv[3]);
            *(float4*)(g_acc + gi * 128 + tx * 8 + 4) = make_float4(acv[4], acv[5], acv[6], acv[7]);
        }
    }
}

// ---------------- launch -------------------------------------------------------
extern "C" void kernel_launch(void* const* d_in, const int* in_sizes, int n_in,
                              void* d_out, int out_size) {
    const float* x    = (const float*)d_in[0];
    const int*   ei   = (const int*)d_in[1];
    const float* ew   = (const float*)d_in[2];
    const int*   nn   = (const int*)d_in[3];
    const float* Wq_w = (const float*)d_in[4];
    const float* Wq_b = (const float*)d_in[5];
    const float* Wk_w = (const float*)d_in[6];
    const float* Wk_b = (const float*)d_in[7];
    const float* Wo_w = (const float*)d_in[8];
    const float* Wo_b = (const float*)d_in[9];

    int N = in_sizes[0] / 128;
    int E = in_sizes[1] / 2;
    int B = in_sizes[3];
    const int* row = ei;
    const int* col = ei + E;

    int gN = (N + 255) / 256;
    int gE = (E + 255) / 256;

    // preprocessing
    k_offsets<<<1, 32>>>(nn, B);
    k_batch<<<gN, 256>>>(N, B);          // also zeroes g_dinv / g_cnt
    k_degcnt<<<gE, 256>>>(row, ew, E);
    k_dinv<<<gN, 256>>>(N);
    k_scan1<<<(N + 511) / 512, 512>>>(N);
    k_scan2<<<1, 64>>>((N + 511) / 512);
    k_scan3<<<gN, 256>>>(N);
    k_cursor<<<gN, 256>>>(N);
    k_scatter<<<gE, 256>>>(row, col, ew, E);

    // q, k projections + normalize; iteration-invariant denom
    int gG = (N + 127) / 128;
    k_gemm<<<gG, 256>>>(x, 0, Wq_w, Wq_b, nullptr, 0, N);
    k_norm<<<(N + 7) / 8, 256>>>(0, N);
    k_gemm<<<gG, 256>>>(x, 0, Wk_w, Wk_b, nullptr, 1, N);
    k_norm<<<(N + 7) / 8, 256>>>(1, N);
    k_ksum<<<B, 512>>>();
    k_denom<<<(N + 7) / 8, 256>>>(N);

    // cur = acc = x
    k_init<<<(N * 128 + 255) / 256, 256>>>(x, N * 128);

    // 4 propagation iterations
    for (int it = 0; it < 4; it++) {
        int cs = it & 1;
        k_gcn<<<(N + 7) / 8, 256>>>(cs, N);
        dim3 gkv(B, KVS);
        k_kv<<<gkv, 256>>>(cs);
        dim3 gred(B, 129);
        k_kvred<<<gred, 128>>>();
        dim3 g(gG, B);
        k_numer<<<g, 256>>>(cs);
    }

    // out = acc @ Wo^T + bias  (H=1 so /H is a no-op)
    k_gemm<<<gG, 256>>>(nullptr, 1, Wo_w, Wo_b, (float*)d_out, 2, N);
}

// round 10
// speedup vs baseline: 1.8244x; 1.1777x over previous
#include <cuda_runtime.h>
#include <cuda_bf16.h>

#define MAXN 32768
#define MAXE 524288
#define MAXB 64
#define KVS 4     // split-K factor for k_kv
#define MAXT 512  // max numer tiles

// ---------------- scratch (device globals; no allocation allowed) -------------
__device__ float g_qs[MAXN * 128];
__device__ float g_ks[MAXN * 128];
__device__ float g_curA[MAXN * 128];
__device__ float g_curB[MAXN * 128];
__device__ float g_acc[MAXN * 128];
__device__ float g_KV[MAXB * 128 * 128];
__device__ float g_KVp[KVS * MAXB * 128 * 128];
__device__ float g_vsum[MAXB * 128];
__device__ float g_vsump[KVS * MAXB * 128];
__device__ float g_denom[MAXN];
__device__ float g_dinv[MAXN];
__device__ float g_coef[MAXE];
__device__ int   g_ccol[MAXE];
__device__ int   g_cnt[MAXN];
__device__ int   g_rp[MAXN + 1];
__device__ int   g_curs[MAXN];
__device__ int   g_off[MAXB + 1];
__device__ int   g_batch[MAXN];
__device__ int   g_bsum[MAXB];
__device__ int   g_tileB[MAXT];
__device__ int   g_tileR[MAXT];
__device__ int   g_ntiles;

// ---------------- f32x2 helpers ------------------------------------------------
#define FMA2(acc, a, b) \
    asm("fma.rn.f32x2 %0, %1, %2, %0;" : "+l"(acc) : "l"(a), "l"(b))

__device__ __forceinline__ unsigned long long pk2(float v) {
    unsigned long long d;
    unsigned int u = __float_as_uint(v);
    asm("mov.b64 %0, {%1, %1};" : "=l"(d) : "r"(u));
    return d;
}
__device__ __forceinline__ void upk2(unsigned long long v, float& lo, float& hi) {
    unsigned int a, b;
    asm("mov.b64 {%0, %1}, %2;" : "=r"(a), "=r"(b) : "l"(v));
    lo = __uint_as_float(a); hi = __uint_as_float(b);
}

// ---------------- preprocessing ------------------------------------------------
// single-thread: offsets + numer tile worklist
__global__ void k_offsets(const int* __restrict__ n_nodes, int B) {
    if (threadIdx.x == 0 && blockIdx.x == 0) {
        int s = 0;
        g_off[0] = 0;
        int t = 0;
        for (int b = 0; b < B; b++) {
            int nb = n_nodes[b];
            for (int r0 = 0; r0 < nb; r0 += 128) {
                g_tileB[t] = b; g_tileR[t] = r0; t++;
            }
            s += nb; g_off[b + 1] = s;
        }
        g_ntiles = t;
    }
}

// batch id per node + zero init for degree/count
__global__ void k_batch(int N, int B) {
    int i = blockIdx.x * blockDim.x + threadIdx.x;
    if (i >= N) return;
    int lo = 0, hi = B;
    while (hi - lo > 1) {
        int mid = (lo + hi) >> 1;
        if (g_off[mid] <= i) lo = mid; else hi = mid;
    }
    g_batch[i] = lo;
    g_dinv[i] = 0.f;
    g_cnt[i] = 0;
}

__global__ void k_degcnt(const int* __restrict__ row, const float* __restrict__ w, int E) {
    int e = blockIdx.x * blockDim.x + threadIdx.x;
    if (e < E) {
        int r = row[e];
        atomicAdd(&g_dinv[r], w[e]);
        atomicAdd(&g_cnt[r], 1);
    }
}

// block-local inclusive scan of cnt; also finishes dinv (independent elementwise)
__global__ void k_scan1(int N) {
    __shared__ int s[512];
    int t = threadIdx.x;
    int gid = blockIdx.x * 512 + t;
    int v = (gid < N) ? g_cnt[gid] : 0;
    if (gid < N) {
        float d = g_dinv[gid];
        g_dinv[gid] = (d > 0.f) ? rsqrtf(d) : 0.f;
    }
    s[t] = v; __syncthreads();
    #pragma unroll
    for (int o = 1; o < 512; o <<= 1) {
        int add = (t >= o) ? s[t - o] : 0;
        __syncthreads();
        s[t] += add;
        __syncthreads();
    }
    if (gid < N) g_rp[gid + 1] = s[t];
    if (t == 511) g_bsum[blockIdx.x] = s[511];
}

__global__ void k_scan2(int nb) {
    __shared__ int s[64];
    int t = threadIdx.x;
    s[t] = (t < nb) ? g_bsum[t] : 0;
    __syncthreads();
    #pragma unroll
    for (int o = 1; o < 64; o <<= 1) {
        int add = (t >= o) ? s[t - o] : 0;
        __syncthreads();
        s[t] += add;
        __syncthreads();
    }
    if (t < nb) g_bsum[t] = s[t];
}

// finish scan; also init cursors (curs[i] = rp[i] = rp[i+1]-cnt[i])
__global__ void k_scan3(int N) {
    int gid = blockIdx.x * blockDim.x + threadIdx.x;
    if (gid < N) {
        int blk = gid >> 9;
        int add = (blk > 0) ? g_bsum[blk - 1] : 0;
        int rp1 = g_rp[gid + 1] + add;
        g_rp[gid + 1] = rp1;
        g_curs[gid] = rp1 - g_cnt[gid];
        if (gid == 0) g_rp[0] = 0;
    }
}

__global__ void k_scatter(const int* __restrict__ row, const int* __restrict__ col,
                          const float* __restrict__ w, int E) {
    int e = blockIdx.x * blockDim.x + threadIdx.x;
    if (e >= E) return;
    int r = row[e], c = col[e];
    int p = atomicAdd(&g_curs[r], 1);
    g_ccol[p] = c;
    g_coef[p] = g_dinv[r] * g_dinv[c] * w[e];
}

// ---------------- fused Q/K projection GEMM + bias + row-L2-norm (+init) ------
// grid (gG, 2): y=0 -> Q (also copies x into curA/acc), y=1 -> K.
__global__ __launch_bounds__(256) void k_gemmqk(
    const float* __restrict__ x,
    const float* __restrict__ Wq, const float* __restrict__ bq,
    const float* __restrict__ Wk, const float* __restrict__ bk,
    int M)
{
    int which = blockIdx.y;
    const float* W    = which ? Wk : Wq;
    const float* bias = which ? bk : bq;
    float* Cout       = which ? g_ks : g_qs;

    __shared__ __align__(16) float As[16][128];
    __shared__ __align__(16) float Bs[16][132];

    int tid = threadIdx.x;
    int tx = tid & 15, ty = tid >> 4;
    int r0 = blockIdx.x * 128;

    unsigned long long acc2[8][4];
    #pragma unroll
    for (int r = 0; r < 8; r++)
        #pragma unroll
        for (int c = 0; c < 4; c++) acc2[r][c] = 0ULL;

    for (int k0 = 0; k0 < 128; k0 += 16) {
        #pragma unroll
        for (int it = 0; it < 2; it++) {
            int id = tid + it * 256;
            int rowi = id >> 2, k4 = id & 3;
            int gr = r0 + rowi;
            float4 v = make_float4(0.f, 0.f, 0.f, 0.f);
            if (gr < M) v = *(const float4*)(x + gr * 128 + k0 + k4 * 4);
            As[k4 * 4 + 0][rowi] = v.x;
            As[k4 * 4 + 1][rowi] = v.y;
            As[k4 * 4 + 2][rowi] = v.z;
            As[k4 * 4 + 3][rowi] = v.w;
        }
        #pragma unroll
        for (int it = 0; it < 8; it++) {
            int id = tid + it * 256;
            int kk = id & 15, j = id >> 4;
            Bs[kk][j] = W[j * 128 + k0 + kk];
        }
        __syncthreads();
        #pragma unroll
        for (int kk = 0; kk < 16; kk++) {
            float4 a0 = *(const float4*)(&As[kk][ty * 8]);
            float4 a1 = *(const float4*)(&As[kk][ty * 8 + 4]);
            ulonglong2 bA = *(const ulonglong2*)(&Bs[kk][tx * 8]);
            ulonglong2 bB = *(const ulonglong2*)(&Bs[kk][tx * 8 + 4]);
            float av[8] = {a0.x, a0.y, a0.z, a0.w, a1.x, a1.y, a1.z, a1.w};
            #pragma unroll
            for (int r = 0; r < 8; r++) {
                unsigned long long ap = pk2(av[r]);
                FMA2(acc2[r][0], ap, bA.x);
                FMA2(acc2[r][1], ap, bA.y);
                FMA2(acc2[r][2], ap, bB.x);
                FMA2(acc2[r][3], ap, bB.y);
            }
        }
        __syncthreads();
    }

    float4 bs0 = *(const float4*)(bias + tx * 8);
    float4 bs1 = *(const float4*)(bias + tx * 8 + 4);

    #pragma unroll
    for (int r = 0; r < 8; r++) {
        int gr = r0 + ty * 8 + r;
        if (gr >= M) continue;
        float o[8];
        upk2(acc2[r][0], o[0], o[1]);
        upk2(acc2[r][1], o[2], o[3]);
        upk2(acc2[r][2], o[4], o[5]);
        upk2(acc2[r][3], o[6], o[7]);
        o[0] += bs0.x; o[1] += bs0.y; o[2] += bs0.z; o[3] += bs0.w;
        o[4] += bs1.x; o[5] += bs1.y; o[6] += bs1.z; o[7] += bs1.w;
        // row L2 norm: 16 lanes (same ty) hold the 128 cols of this row
        float ss = 0.f;
        #pragma unroll
        for (int c = 0; c < 8; c++) ss += o[c] * o[c];
        #pragma unroll
        for (int off = 1; off < 16; off <<= 1)
            ss += __shfl_xor_sync(0xFFFFFFFFu, ss, off);
        float rn = rsqrtf(ss);
        #pragma unroll
        for (int c = 0; c < 8; c++) o[c] *= rn;
        *(float4*)(Cout + gr * 128 + tx * 8)     = make_float4(o[0], o[1], o[2], o[3]);
        *(float4*)(Cout + gr * 128 + tx * 8 + 4) = make_float4(o[4], o[5], o[6], o[7]);
        if (which == 0) {   // init cur = acc = x
            float4 x0 = *(const float4*)(x + gr * 128 + tx * 8);
            float4 x1 = *(const float4*)(x + gr * 128 + tx * 8 + 4);
            *(float4*)(g_curA + gr * 128 + tx * 8)     = x0;
            *(float4*)(g_curA + gr * 128 + tx * 8 + 4) = x1;
            *(float4*)(g_acc + gr * 128 + tx * 8)      = x0;
            *(float4*)(g_acc + gr * 128 + tx * 8 + 4)  = x1;
        }
    }
}

// ---------------- ksum per graph + denom for that graph's nodes ----------------
__global__ __launch_bounds__(512) void k_ksumdenom() {
    __shared__ float red[512];
    __shared__ float sks[128];
    int b = blockIdx.x;
    int tid = threadIdx.x;
    int d = tid & 127, c = tid >> 7;
    int off = g_off[b], nb = g_off[b + 1] - off;
    float s = 0.f;
    for (int n = c; n < nb; n += 4) s += g_ks[(off + n) * 128 + d];
    red[c * 128 + d] = s;
    __syncthreads();
    if (tid < 128)
        sks[tid] = red[tid] + red[tid + 128] + red[tid + 256] + red[tid + 384];
    __syncthreads();

    int w = tid >> 5, lane = tid & 31;
    float4 kk = *(const float4*)(&sks[lane * 4]);
    float nbf = (float)nb;
    for (int n = w; n < nb; n += 16) {
        int gi = off + n;
        float4 q = *(const float4*)(g_qs + gi * 128 + lane * 4);
        float t = q.x * kk.x + q.y * kk.y + q.z * kk.z + q.w * kk.w;
        #pragma unroll
        for (int o = 16; o > 0; o >>= 1) t += __shfl_xor_sync(0xFFFFFFFFu, t, o);
        if (lane == 0) g_denom[gi] = t + nbf;
    }
}

// ---------------- split-K partial KV = K^T V per graph + V column sums --------
__global__ __launch_bounds__(256) void k_kv(int curSel) {
    const float* cur = curSel ? g_curB : g_curA;
    __shared__ __align__(16) float Ks[16][132];
    __shared__ __align__(16) float Vs[16][132];
    __shared__ float vs[128];
    int b = blockIdx.x, sp = blockIdx.y;
    int off = g_off[b], nb = g_off[b + 1] - off;
    int chunk = (nb + KVS - 1) / KVS;
    int s0 = sp * chunk;
    int lim = s0 + chunk; if (lim > nb) lim = nb;

    int tid = threadIdx.x, tx = tid & 15, ty = tid >> 4;

    if (tid < 128) vs[tid] = 0.f;
    __syncthreads();

    unsigned long long acc2[8][4];
    #pragma unroll
    for (int r = 0; r < 8; r++)
        #pragma unroll
        for (int c = 0; c < 4; c++) acc2[r][c] = 0ULL;
    float4 vpart = make_float4(0.f, 0.f, 0.f, 0.f);

    for (int k0 = s0; k0 < lim; k0 += 16) {
        #pragma unroll
        for (int it = 0; it < 2; it++) {
            int id = tid + it * 256;
            int kk = id >> 5, dd = id & 31;
            int rl = k0 + kk;
            float4 kv = make_float4(0.f, 0.f, 0.f, 0.f);
            float4 vv = make_float4(0.f, 0.f, 0.f, 0.f);
            if (rl < lim) {
                kv = *(const float4*)(g_ks + (off + rl) * 128 + dd * 4);
                vv = *(const float4*)(cur + (off + rl) * 128 + dd * 4);
            }
            *(float4*)(&Ks[kk][dd * 4]) = kv;
            *(float4*)(&Vs[kk][dd * 4]) = vv;
            vpart.x += vv.x; vpart.y += vv.y; vpart.z += vv.z; vpart.w += vv.w;
        }
        __syncthreads();
        #pragma unroll
        for (int kk = 0; kk < 16; kk++) {
            float4 a0 = *(const float4*)(&Ks[kk][ty * 8]);
            float4 a1 = *(const float4*)(&Ks[kk][ty * 8 + 4]);
            ulonglong2 bA = *(const ulonglong2*)(&Vs[kk][tx * 8]);
            ulonglong2 bB = *(const ulonglong2*)(&Vs[kk][tx * 8 + 4]);
            float av[8] = {a0.x, a0.y, a0.z, a0.w, a1.x, a1.y, a1.z, a1.w};
            #pragma unroll
            for (int r = 0; r < 8; r++) {
                unsigned long long ap = pk2(av[r]);
                FMA2(acc2[r][0], ap, bA.x);
                FMA2(acc2[r][1], ap, bA.y);
                FMA2(acc2[r][2], ap, bB.x);
                FMA2(acc2[r][3], ap, bB.y);
            }
        }
        __syncthreads();
    }

    float* out = g_KVp + (sp * MAXB + b) * 16384;
    #pragma unroll
    for (int r = 0; r < 8; r++) {
        int cr = ty * 8 + r;
        float o[8];
        upk2(acc2[r][0], o[0], o[1]);
        upk2(acc2[r][1], o[2], o[3]);
        upk2(acc2[r][2], o[4], o[5]);
        upk2(acc2[r][3], o[6], o[7]);
        *(float4*)(out + cr * 128 + tx * 8)     = make_float4(o[0], o[1], o[2], o[3]);
        *(float4*)(out + cr * 128 + tx * 8 + 4) = make_float4(o[4], o[5], o[6], o[7]);
    }

    int d4 = tid & 31;
    atomicAdd(&vs[d4 * 4 + 0], vpart.x);
    atomicAdd(&vs[d4 * 4 + 1], vpart.y);
    atomicAdd(&vs[d4 * 4 + 2], vpart.z);
    atomicAdd(&vs[d4 * 4 + 3], vpart.w);
    __syncthreads();
    if (tid < 128) g_vsump[(sp * MAXB + b) * 128 + tid] = vs[tid];
}

// ---------------- reduce split-K partials -------------------------------------
__global__ void k_kvred() {
    int b = blockIdx.x, r = blockIdx.y, t = threadIdx.x;
    if (r < 128) {
        float s = 0.f;
        #pragma unroll
        for (int sp = 0; sp < KVS; sp++)
            s += g_KVp[(sp * MAXB + b) * 16384 + r * 128 + t];
        g_KV[b * 16384 + r * 128 + t] = s;
    } else {
        float s = 0.f;
        #pragma unroll
        for (int sp = 0; sp < KVS; sp++)
            s += g_vsump[(sp * MAXB + b) * 128 + t];
        g_vsum[b * 128 + t] = s;
    }
}

// ---------------- numer = Q @ KV, fused GCN gather + combine + accumulate -----
// flat tile worklist grid; epilogue does the CSR gather (replaces k_gcn).
__global__ __launch_bounds__(256) void k_numer(int curSel) {
    const float* cur = curSel ? g_curB : g_curA;
    float* nxt       = curSel ? g_curA : g_curB;
    __shared__ __align__(16) float As[16][128];
    __shared__ __align__(16) float Bs[16][132];

    int t = blockIdx.x;
    if (t >= g_ntiles) return;
    int b = g_tileB[t];
    int r0 = g_tileR[t];
    int off = g_off[b], nb = g_off[b + 1] - off;
    int base = off + r0;
    int m = nb - r0; if (m > 128) m = 128;

    const float* KVb = g_KV + b * 16384;
    int tid = threadIdx.x, tx = tid & 15, ty = tid >> 4;

    unsigned long long acc2[8][4];
    #pragma unroll
    for (int r = 0; r < 8; r++)
        #pragma unroll
        for (int c = 0; c < 4; c++) acc2[r][c] = 0ULL;

    for (int k0 = 0; k0 < 128; k0 += 16) {
        #pragma unroll
        for (int it = 0; it < 2; it++) {
            int id = tid + it * 256;
            int rowi = id >> 2, k4 = id & 3;
            float4 v = make_float4(0.f, 0.f, 0.f, 0.f);
            if (rowi < m) v = *(const float4*)(g_qs + (base + rowi) * 128 + k0 + k4 * 4);
            As[k4 * 4 + 0][rowi] = v.x;
            As[k4 * 4 + 1][rowi] = v.y;
            As[k4 * 4 + 2][rowi] = v.z;
            As[k4 * 4 + 3][rowi] = v.w;
        }
        #pragma unroll
        for (int it = 0; it < 2; it++) {
            int id = tid + it * 256;
            int kk = id >> 5, j4 = id & 31;
            float4 v = *(const float4*)(KVb + (k0 + kk) * 128 + j4 * 4);
            *(float4*)(&Bs[kk][j4 * 4]) = v;
        }
        __syncthreads();
        #pragma unroll
        for (int kk = 0; kk < 16; kk++) {
            float4 a0 = *(const float4*)(&As[kk][ty * 8]);
            float4 a1 = *(const float4*)(&As[kk][ty * 8 + 4]);
            ulonglong2 bA = *(const ulonglong2*)(&Bs[kk][tx * 8]);
            ulonglong2 bB = *(const ulonglong2*)(&Bs[kk][tx * 8 + 4]);
            float av[8] = {a0.x, a0.y, a0.z, a0.w, a1.x, a1.y, a1.z, a1.w};
            #pragma unroll
            for (int r = 0; r < 8; r++) {
                unsigned long long ap = pk2(av[r]);
                FMA2(acc2[r][0], ap, bA.x);
                FMA2(acc2[r][1], ap, bA.y);
                FMA2(acc2[r][2], ap, bB.x);
                FMA2(acc2[r][3], ap, bB.y);
            }
        }
        __syncthreads();
    }

    float4 vs0 = *(const float4*)(g_vsum + b * 128 + tx * 8);
    float4 vs1 = *(const float4*)(g_vsum + b * 128 + tx * 8 + 4);
    float vsv[8] = {vs0.x, vs0.y, vs0.z, vs0.w, vs1.x, vs1.y, vs1.z, vs1.w};

    #pragma unroll
    for (int r = 0; r < 8; r++) {
        int rowi = ty * 8 + r;
        if (rowi >= m) continue;
        int gi = base + rowi;
        float inv = 1.f / g_denom[gi];
        float o[8];
        upk2(acc2[r][0], o[0], o[1]);
        upk2(acc2[r][1], o[2], o[3]);
        upk2(acc2[r][2], o[4], o[5]);
        upk2(acc2[r][3], o[6], o[7]);

        // fused GCN gather for this row's 8 columns
        float gc[8] = {0.f, 0.f, 0.f, 0.f, 0.f, 0.f, 0.f, 0.f};
        int ps = g_rp[gi], pe = g_rp[gi + 1];
        #pragma unroll 4
        for (int p = ps; p < pe; p++) {
            float cf = g_coef[p];
            int cl = g_ccol[p];
            float4 v0 = *(const float4*)(cur + cl * 128 + tx * 8);
            float4 v1 = *(const float4*)(cur + cl * 128 + tx * 8 + 4);
            gc[0] += cf * v0.x; gc[1] += cf * v0.y; gc[2] += cf * v0.z; gc[3] += cf * v0.w;
            gc[4] += cf * v1.x; gc[5] += cf * v1.y; gc[6] += cf * v1.z; gc[7] += cf * v1.w;
        }

        float4 ac0 = *(const float4*)(g_acc + gi * 128 + tx * 8);
        float4 ac1 = *(const float4*)(g_acc + gi * 128 + tx * 8 + 4);
        float acv[8] = {ac0.x, ac0.y, ac0.z, ac0.w, ac1.x, ac1.y, ac1.z, ac1.w};
        float nv[8];
        #pragma unroll
        for (int c = 0; c < 8; c++) {
            float attn = (o[c] + vsv[c]) * inv;
            nv[c] = 0.5f * gc[c] + 0.5f * attn;
            acv[c] += nv[c];
        }
        *(float4*)(nxt + gi * 128 + tx * 8)       = make_float4(nv[0], nv[1], nv[2], nv[3]);
        *(float4*)(nxt + gi * 128 + tx * 8 + 4)   = make_float4(nv[4], nv[5], nv[6], nv[7]);
        *(float4*)(g_acc + gi * 128 + tx * 8)     = make_float4(acv[0], acv[1], acv[2], acv[3]);
        *(float4*)(g_acc + gi * 128 + tx * 8 + 4) = make_float4(acv[4], acv[5], acv[6], acv[7]);
    }
}

// ---------------- final GEMM: out = acc @ Wo^T + bias --------------------------
__global__ __launch_bounds__(256) void k_gemmo(
    const float* __restrict__ W, const float* __restrict__ bias,
    float* __restrict__ Cout, int M)
{
    __shared__ __align__(16) float As[16][128];
    __shared__ __align__(16) float Bs[16][132];

    int tid = threadIdx.x;
    int tx = tid & 15, ty = tid >> 4;
    int r0 = blockIdx.x * 128;

    unsigned long long acc2[8][4];
    #pragma unroll
    for (int r = 0; r < 8; r++)
        #pragma unroll
        for (int c = 0; c < 4; c++) acc2[r][c] = 0ULL;

    for (int k0 = 0; k0 < 128; k0 += 16) {
        #pragma unroll
        for (int it = 0; it < 2; it++) {
            int id = tid + it * 256;
            int rowi = id >> 2, k4 = id & 3;
            int gr = r0 + rowi;
            float4 v = make_float4(0.f, 0.f, 0.f, 0.f);
            if (gr < M) v = *(const float4*)(g_acc + gr * 128 + k0 + k4 * 4);
            As[k4 * 4 + 0][rowi] = v.x;
            As[k4 * 4 + 1][rowi] = v.y;
            As[k4 * 4 + 2][rowi] = v.z;
            As[k4 * 4 + 3][rowi] = v.w;
        }
        #pragma unroll
        for (int it = 0; it < 8; it++) {
            int id = tid + it * 256;
            int kk = id & 15, j = id >> 4;
            Bs[kk][j] = W[j * 128 + k0 + kk];
        }
        __syncthreads();
        #pragma unroll
        for (int kk = 0; kk < 16; kk++) {
            float4 a0 = *(const float4*)(&As[kk][ty * 8]);
            float4 a1 = *(const float4*)(&As[kk][ty * 8 + 4]);
            ulonglong2 bA = *(const ulonglong2*)(&Bs[kk][tx * 8]);
            ulonglong2 bB = *(const ulonglong2*)(&Bs[kk][tx * 8 + 4]);
            float av[8] = {a0.x, a0.y, a0.z, a0.w, a1.x, a1.y, a1.z, a1.w};
            #pragma unroll
            for (int r = 0; r < 8; r++) {
                unsigned long long ap = pk2(av[r]);
                FMA2(acc2[r][0], ap, bA.x);
                FMA2(acc2[r][1], ap, bA.y);
                FMA2(acc2[r][2], ap, bB.x);
                FMA2(acc2[r][3], ap, bB.y);
            }
        }
        __syncthreads();
    }

    float4 bs0 = *(const float4*)(bias + tx * 8);
    float4 bs1 = *(const float4*)(bias + tx * 8 + 4);
    #pragma unroll
    for (int r = 0; r < 8; r++) {
        int gr = r0 + ty * 8 + r;
        if (gr < M) {
            float o[8];
            upk2(acc2[r][0], o[0], o[1]);
            upk2(acc2[r][1], o[2], o[3]);
            upk2(acc2[r][2], o[4], o[5]);
            upk2(acc2[r][3], o[6], o[7]);
            *(float4*)(Cout + gr * 128 + tx * 8) =
                make_float4(o[0] + bs0.x, o[1] + bs0.y, o[2] + bs0.z, o[3] + bs0.w);
            *(float4*)(Cout + gr * 128 + tx * 8 + 4) =
                make_float4(o[4] + bs1.x, o[5] + bs1.y, o[6] + bs1.z, o[7] + bs1.w);
        }
    }
}

// ---------------- launch -------------------------------------------------------
extern "C" void kernel_launch(void* const* d_in, const int* in_sizes, int n_in,
                              void* d_out, int out_size) {
    const float* x    = (const float*)d_in[0];
    const int*   ei   = (const int*)d_in[1];
    const float* ew   = (const float*)d_in[2];
    const int*   nn   = (const int*)d_in[3];
    const float* Wq_w = (const float*)d_in[4];
    const float* Wq_b = (const float*)d_in[5];
    const float* Wk_w = (const float*)d_in[6];
    const float* Wk_b = (const float*)d_in[7];
    const float* Wo_w = (const float*)d_in[8];
    const float* Wo_b = (const float*)d_in[9];

    int N = in_sizes[0] / 128;
    int E = in_sizes[1] / 2;
    int B = in_sizes[3];
    const int* row = ei;
    const int* col = ei + E;

    int gN = (N + 255) / 256;
    int gE = (E + 255) / 256;
    int gG = (N + 127) / 128;

    // preprocessing (7 launches)
    k_offsets<<<1, 32>>>(nn, B);
    k_batch<<<gN, 256>>>(N, B);
    k_degcnt<<<gE, 256>>>(row, ew, E);
    k_scan1<<<(N + 511) / 512, 512>>>(N);
    k_scan2<<<1, 64>>>((N + 511) / 512);
    k_scan3<<<gN, 256>>>(N);
    k_scatter<<<gE, 256>>>(row, col, ew, E);

    // q/k projections (+bias, norm, init) in one launch; then ksum+denom
    dim3 gqk(gG, 2);
    k_gemmqk<<<gqk, 256>>>(x, Wq_w, Wq_b, Wk_w, Wk_b, N);
    k_ksumdenom<<<B, 512>>>();

    // 4 propagation iterations (3 launches each)
    int ntile_max = gG + B;   // upper bound on device-side tile count
    for (int it = 0; it < 4; it++) {
        int cs = it & 1;
        dim3 gkv(B, KVS);
        k_kv<<<gkv, 256>>>(cs);
        dim3 gred(B, 129);
        k_kvred<<<gred, 128>>>();
        k_numer<<<ntile_max, 256>>>(cs);
    }

    // out = acc @ Wo^T + bias (H=1 so /H is a no-op)
    k_gemmo<<<gG, 256>>>(Wo_w, Wo_b, (float*)d_out, N);
}